// round 3
// baseline (speedup 1.0000x reference)
#include <cuda_runtime.h>

#define N_NODES 200000
#define N_EDGES 800000
#define D 128

typedef unsigned long long u64;

// Scratch (allocation-free rule: __device__ globals).
__device__ float g_agg[(size_t)N_NODES * D];
__device__ float g_W1T[256 * 128];   // [c][k], c=0..127, k=0..255
__device__ float g_W2T[128 * 128];   // [c][k]

// ---------------- packed f32x2 helpers ----------------
__device__ __forceinline__ u64 ffma2(u64 a, u64 b, u64 c) {
    u64 d;
    asm("fma.rn.f32x2 %0, %1, %2, %3;" : "=l"(d) : "l"(a), "l"(b), "l"(c));
    return d;
}
__device__ __forceinline__ void unpack2(u64 v, float& lo, float& hi) {
    asm("mov.b64 {%0, %1}, %2;" : "=f"(lo), "=f"(hi) : "l"(v));
}

// ---------------------------------------------------------------------------
// Kernel 0: transpose weights into [c][k] layout (runs once, tiny).
// ---------------------------------------------------------------------------
__global__ void transpose_W_kernel(const float* __restrict__ W1,
                                   const float* __restrict__ W2) {
    int i = blockIdx.x * blockDim.x + threadIdx.x;
    if (i < 128 * 256) {
        int k = i & 255, c = i >> 8;
        g_W1T[c * 256 + k] = W1[k * 128 + c];
    }
    if (i < 128 * 128) {
        int k = i & 127, c = i >> 7;
        g_W2T[c * 128 + k] = W2[k * 128 + c];
    }
}

// ---------------------------------------------------------------------------
// Kernel 1: zero aggregation buffer.
// ---------------------------------------------------------------------------
__global__ void zero_agg_kernel() {
    size_t i = (size_t)blockIdx.x * blockDim.x + threadIdx.x;
    size_t n = (size_t)N_NODES * D / 4;
    if (i < n) ((float4*)g_agg)[i] = make_float4(0.f, 0.f, 0.f, 0.f);
}

// ---------------------------------------------------------------------------
// Kernel 2: scatter-add edge_attr onto receiver nodes (int32 indices).
// ---------------------------------------------------------------------------
__global__ void scatter_kernel(const float* __restrict__ edge_attr,
                               const int* __restrict__ recv) {
    unsigned idx = blockIdx.x * blockDim.x + threadIdx.x;
    if (idx >= (unsigned)N_EDGES * 32u) return;
    unsigned e = idx >> 5;
    unsigned q = idx & 31u;
    int r = __ldg(recv + e);
    float4 v = ((const float4*)edge_attr)[(size_t)e * 32 + q];
    float* dst = g_agg + (size_t)r * D + (size_t)q * 4;
    atomicAdd(dst + 0, v.x);
    atomicAdd(dst + 1, v.y);
    atomicAdd(dst + 2, v.z);
    atomicAdd(dst + 3, v.w);
}

// ---------------------------------------------------------------------------
// Kernel 3: fused MLP with packed fp32x2 FMAs, K-pair packing.
//   h   = relu([x | agg] @ W1 + b1)   (K = 256)
//   out = h @ W2 + b2                 (K = 128)
//
// 256 threads, 64 nodes/CTA. Thread (tx,ty) owns 8 nodes x 4 cols.
// Accumulator u64 halves hold (sum over k-pair-lo, k-pair-hi); summed in
// the epilogue. W in smem is [c][k] with XOR-swizzled 16B granules
// (f4 ^ ((c>>2)&7)) so per-c LDS.128 across the warp is conflict-free.
// Shared (192 KB): sW2T 64K | sW1c 32K | sA 64K | sH 32K.
// ---------------------------------------------------------------------------
__global__ __launch_bounds__(256) void mlp_kernel(
    const float* __restrict__ x,
    const float* __restrict__ b1,
    const float* __restrict__ b2,
    float* __restrict__ out) {

    extern __shared__ float smem[];
    float4* sW2T = (float4*)smem;       // 4096 f4: [c][32 f4], swizzled
    float4* sW1c = sW2T + 4096;         // 2048 f4: [c][16 f4], swizzled (K-chunk)
    float4* sA   = sW1c + 2048;         // 4096 f4: [m][64 f4], plain
    float4* sH   = sA   + 4096;         // 2048 f4: [m][32 f4], plain

    const int tid = threadIdx.x;
    const int tx = tid & 31;            // cols 4*tx .. 4*tx+3
    const int ty = tid >> 5;            // nodes 8*ty .. 8*ty+7
    const int s  = tx & 7;              // swizzle key = (c>>2)&7
    const int node0 = blockIdx.x * 64;

    // Fill sW2T (resident, swizzled).
    const float4* W2Tg = (const float4*)g_W2T;
    #pragma unroll 4
    for (int i = tid; i < 4096; i += 256) {
        int c = i >> 5, f4 = i & 31;
        sW2T[c * 32 + (f4 ^ ((c >> 2) & 7))] = W2Tg[i];
    }

    // Fill sA: per node, k[0:128)=x, k[128:256)=agg.
    #pragma unroll 4
    for (int i = tid; i < 4096; i += 256) {
        int m = i >> 6, f = i & 63;
        size_t node = (size_t)(node0 + m);
        float4 v = (f < 32) ? ((const float4*)x)[node * 32 + f]
                            : ((const float4*)g_agg)[node * 32 + (f - 32)];
        sA[m * 64 + f] = v;
    }

    u64 acc[8][4];
    #pragma unroll
    for (int m = 0; m < 8; ++m)
        #pragma unroll
        for (int c = 0; c < 4; ++c) acc[m][c] = 0ull;

    // ------------------- GEMM1: [64x256] @ [256x128] -------------------
    const float4* W1Tg = (const float4*)g_W1T;   // [c][64 f4]
    for (int kc = 0; kc < 4; ++kc) {
        #pragma unroll 4
        for (int i = tid; i < 2048; i += 256) {
            int c = i >> 4, f4 = i & 15;
            sW1c[c * 16 + (f4 ^ ((c >> 2) & 7))] = W1Tg[c * 64 + kc * 16 + f4];
        }
        __syncthreads();   // also orders sA/sW2T on first iter

        #pragma unroll
        for (int kb = 0; kb < 64; kb += 8) {
            const int f40 = kb >> 2;
            ulonglong2 w[4][2];
            #pragma unroll
            for (int cc = 0; cc < 4; ++cc) {
                const float4* base = sW1c + (4 * tx + cc) * 16;
                w[cc][0] = *(const ulonglong2*)&base[f40 ^ s];
                w[cc][1] = *(const ulonglong2*)&base[(f40 + 1) ^ s];
            }
            #pragma unroll
            for (int m = 0; m < 8; ++m) {
                const float4* arow = sA + (ty * 8 + m) * 64 + kc * 16;
                ulonglong2 a0 = *(const ulonglong2*)&arow[f40];
                ulonglong2 a1 = *(const ulonglong2*)&arow[f40 + 1];
                #pragma unroll
                for (int cc = 0; cc < 4; ++cc) {
                    acc[m][cc] = ffma2(a0.x, w[cc][0].x, acc[m][cc]);
                    acc[m][cc] = ffma2(a0.y, w[cc][0].y, acc[m][cc]);
                    acc[m][cc] = ffma2(a1.x, w[cc][1].x, acc[m][cc]);
                    acc[m][cc] = ffma2(a1.y, w[cc][1].y, acc[m][cc]);
                }
            }
        }
        __syncthreads();
    }

    // Epilogue 1: halves-sum + bias + ReLU -> sH
    {
        float4 b1v = ((const float4*)b1)[tx];
        #pragma unroll
        for (int m = 0; m < 8; ++m) {
            float lo, hi;
            float4 h;
            unpack2(acc[m][0], lo, hi); h.x = fmaxf(lo + hi + b1v.x, 0.f);
            unpack2(acc[m][1], lo, hi); h.y = fmaxf(lo + hi + b1v.y, 0.f);
            unpack2(acc[m][2], lo, hi); h.z = fmaxf(lo + hi + b1v.z, 0.f);
            unpack2(acc[m][3], lo, hi); h.w = fmaxf(lo + hi + b1v.w, 0.f);
            sH[(ty * 8 + m) * 32 + tx] = h;
            acc[m][0] = 0ull; acc[m][1] = 0ull; acc[m][2] = 0ull; acc[m][3] = 0ull;
        }
    }
    __syncthreads();

    // ------------------- GEMM2: [64x128] @ [128x128] -------------------
    #pragma unroll
    for (int kb = 0; kb < 128; kb += 8) {
        const int f40 = kb >> 2;
        ulonglong2 w[4][2];
        #pragma unroll
        for (int cc = 0; cc < 4; ++cc) {
            const float4* base = sW2T + (4 * tx + cc) * 32;
            w[cc][0] = *(const ulonglong2*)&base[f40 ^ s];
            w[cc][1] = *(const ulonglong2*)&base[(f40 + 1) ^ s];
        }
        #pragma unroll
        for (int m = 0; m < 8; ++m) {
            const float4* arow = sH + (ty * 8 + m) * 32;
            ulonglong2 a0 = *(const ulonglong2*)&arow[f40];
            ulonglong2 a1 = *(const ulonglong2*)&arow[f40 + 1];
            #pragma unroll
            for (int cc = 0; cc < 4; ++cc) {
                acc[m][cc] = ffma2(a0.x, w[cc][0].x, acc[m][cc]);
                acc[m][cc] = ffma2(a0.y, w[cc][0].y, acc[m][cc]);
                acc[m][cc] = ffma2(a1.x, w[cc][1].x, acc[m][cc]);
                acc[m][cc] = ffma2(a1.y, w[cc][1].y, acc[m][cc]);
            }
        }
    }

    // Epilogue 2: halves-sum + bias + store
    {
        float4 b2v = ((const float4*)b2)[tx];
        #pragma unroll
        for (int m = 0; m < 8; ++m) {
            size_t node = (size_t)(node0 + ty * 8 + m);
            float lo, hi;
            float4 o;
            unpack2(acc[m][0], lo, hi); o.x = lo + hi + b2v.x;
            unpack2(acc[m][1], lo, hi); o.y = lo + hi + b2v.y;
            unpack2(acc[m][2], lo, hi); o.z = lo + hi + b2v.z;
            unpack2(acc[m][3], lo, hi); o.w = lo + hi + b2v.w;
            ((float4*)out)[node * 32 + tx] = o;
        }
    }
}

// ---------------------------------------------------------------------------
extern "C" void kernel_launch(void* const* d_in, const int* in_sizes, int n_in,
                              void* d_out, int out_size) {
    const float* x          = (const float*)d_in[0];
    const float* edge_attr  = (const float*)d_in[1];
    const int*   edge_index = (const int*)d_in[2];   // int32 (JAX x64 off)
    const float* W1         = (const float*)d_in[3];
    const float* b1         = (const float*)d_in[4];
    const float* W2         = (const float*)d_in[5];
    const float* b2         = (const float*)d_in[6];
    float*       out        = (float*)d_out;

    const int* recv = edge_index + N_EDGES;  // edge_index[1]

    cudaFuncSetAttribute(mlp_kernel,
                         cudaFuncAttributeMaxDynamicSharedMemorySize,
                         196608);

    transpose_W_kernel<<<128, 256>>>(W1, W2);
    zero_agg_kernel<<<25000, 256>>>();
    scatter_kernel<<<100000, 256>>>(edge_attr, recv);
    mlp_kernel<<<3125, 256, 196608>>>(x, b1, b2, out);
}

// round 5
// speedup vs baseline: 2.2754x; 2.2754x over previous
#include <cuda_runtime.h>
#include <cuda_bf16.h>
#include <cstdint>

#define N_NODES 200000
#define N_EDGES 800000
#define D 128

// ---------------------------------------------------------------------------
// Device scratch (allocation-free rule).
// ---------------------------------------------------------------------------
__device__ float g_agg[(size_t)N_NODES * D];
__device__ __nv_bfloat16 g_W1hi[128 * 256];  // W1^T [c][k]
__device__ __nv_bfloat16 g_W1lo[128 * 256];
__device__ __nv_bfloat16 g_W2hi[128 * 128];  // W2^T [c][k]
__device__ __nv_bfloat16 g_W2lo[128 * 128];

// ---------------------------------------------------------------------------
// helpers
// ---------------------------------------------------------------------------
__device__ __forceinline__ uint32_t smem_u32(const void* p) {
    uint32_t a;
    asm("{ .reg .u64 t; cvta.to.shared.u64 t, %1; cvt.u32.u64 %0, t; }"
        : "=r"(a) : "l"(p));
    return a;
}
// pack two floats to bf16x2: lo element = first arg, hi element = second.
__device__ __forceinline__ uint32_t pack_bf16x2(float lo, float hi) {
    uint32_t r;
    asm("cvt.rn.bf16x2.f32 %0, %1, %2;" : "=r"(r) : "f"(hi), "f"(lo));
    return r;
}
// split two floats into hi-bf16x2 and lo-bf16x2 (residual)
__device__ __forceinline__ void split2(float v0, float v1,
                                       uint32_t& hp, uint32_t& lp) {
    hp = pack_bf16x2(v0, v1);
    float h0 = __uint_as_float(hp << 16);
    float h1 = __uint_as_float(hp & 0xffff0000u);
    lp = pack_bf16x2(v0 - h0, v1 - h1);
}

__device__ __forceinline__ void ldsm_x4(uint32_t (&r)[4], uint32_t addr) {
    asm volatile("ldmatrix.sync.aligned.m8n8.x4.shared.b16 {%0,%1,%2,%3}, [%4];"
                 : "=r"(r[0]), "=r"(r[1]), "=r"(r[2]), "=r"(r[3]) : "r"(addr));
}
__device__ __forceinline__ void ldsm_x2(uint32_t (&r)[2], uint32_t addr) {
    asm volatile("ldmatrix.sync.aligned.m8n8.x2.shared.b16 {%0,%1}, [%2];"
                 : "=r"(r[0]), "=r"(r[1]) : "r"(addr));
}
__device__ __forceinline__ void mma_bf16(float (&d)[4], const uint32_t (&a)[4],
                                         const uint32_t (&b)[2]) {
    asm volatile(
        "mma.sync.aligned.m16n8k16.row.col.f32.bf16.bf16.f32 "
        "{%0,%1,%2,%3}, {%4,%5,%6,%7}, {%8,%9}, {%0,%1,%2,%3};"
        : "+f"(d[0]), "+f"(d[1]), "+f"(d[2]), "+f"(d[3])
        : "r"(a[0]), "r"(a[1]), "r"(a[2]), "r"(a[3]), "r"(b[0]), "r"(b[1]));
}

// ---------------------------------------------------------------------------
// Kernel 0: transposed hi/lo bf16 weights.
// ---------------------------------------------------------------------------
__global__ void prep_w_kernel(const float* __restrict__ W1,
                              const float* __restrict__ W2) {
    int i = blockIdx.x * blockDim.x + threadIdx.x;
    if (i < 128 * 256) {
        int c = i >> 8, k = i & 255;
        float v = W1[k * 128 + c];
        __nv_bfloat16 h = __float2bfloat16(v);
        g_W1hi[c * 256 + k] = h;
        g_W1lo[c * 256 + k] = __float2bfloat16(v - __bfloat162float(h));
    }
    if (i < 128 * 128) {
        int c = i >> 7, k = i & 127;
        float v = W2[k * 128 + c];
        __nv_bfloat16 h = __float2bfloat16(v);
        g_W2hi[c * 128 + k] = h;
        g_W2lo[c * 128 + k] = __float2bfloat16(v - __bfloat162float(h));
    }
}

// ---------------------------------------------------------------------------
// Kernel 1: zero agg.
// ---------------------------------------------------------------------------
__global__ void zero_agg_kernel() {
    size_t i = (size_t)blockIdx.x * blockDim.x + threadIdx.x;
    if (i < (size_t)N_NODES * D / 4)
        ((float4*)g_agg)[i] = make_float4(0.f, 0.f, 0.f, 0.f);
}

// ---------------------------------------------------------------------------
// Kernel 2: scatter-add with vector reduction.
// ---------------------------------------------------------------------------
__global__ void scatter_kernel(const float* __restrict__ edge_attr,
                               const int* __restrict__ recv) {
    unsigned idx = blockIdx.x * blockDim.x + threadIdx.x;
    if (idx >= (unsigned)N_EDGES * 32u) return;
    unsigned e = idx >> 5;
    unsigned q = idx & 31u;
    int r = __ldg(recv + e);
    float4 v = ((const float4*)edge_attr)[(size_t)e * 32 + q];
    float* dst = g_agg + (size_t)r * D + (size_t)q * 4;
    asm volatile("red.global.add.v4.f32 [%0], {%1, %2, %3, %4};"
                 :: "l"(dst), "f"(v.x), "f"(v.y), "f"(v.z), "f"(v.w)
                 : "memory");
}

// ---------------------------------------------------------------------------
// Kernel 3: mma.sync bf16 3-term MLP.
//   Per CTA: 128 nodes x 128 cols. 8 warps = 4(M) x 2(N); warp tile 32x64.
//   GEMM1: K=256 in 2 chunks of 128. GEMM2: K=128 (H reuses A buffers).
// SMEM tiles [128][PITCH] bf16, PITCH=136 (272B rows, conflict-free ldmatrix).
// ---------------------------------------------------------------------------
#define PITCH 136
#define TILE_B (128 * PITCH * 2)        // 34816 bytes
#define OFF_A_HI 0
#define OFF_A_LO (OFF_A_HI + TILE_B)
#define OFF_W_HI (OFF_A_LO + TILE_B)
#define OFF_W_LO (OFF_W_HI + TILE_B)
#define OFF_B1   (OFF_W_LO + TILE_B)
#define OFF_B2   (OFF_B1 + 512)
#define SMEM_SZ  (OFF_B2 + 512)

__global__ __launch_bounds__(256) void mma_mlp_kernel(
    const float* __restrict__ x,
    const float* __restrict__ b1,
    const float* __restrict__ b2,
    float* __restrict__ out) {

    extern __shared__ char smem[];
    const uint32_t sb = smem_u32(smem);
    const int tid = threadIdx.x;
    const int lane = tid & 31;
    const int w = tid >> 5;
    const int mw = (w & 3) * 32;          // warp M origin
    const int nw = (w >> 2) * 64;         // warp N origin

    const int node0 = blockIdx.x * 128;
    const int V = min(128, N_NODES - node0);

    float* sB1 = (float*)(smem + OFF_B1);
    float* sB2 = (float*)(smem + OFF_B2);
    if (tid < 128) { sB1[tid] = b1[tid]; sB2[tid] = b2[tid]; }

    // per-thread ldmatrix address components (element units)
    const int arow = lane & 15;           // A: rows m0..m0+15
    const int acol = (lane >> 4) * 8;     // A: k0 or k0+8
    const int brow = lane & 7;            // B: rows n0..n0+7
    const int bcol = ((lane >> 3) & 1) * 8;

    float acc[2][8][4];
    #pragma unroll
    for (int mt = 0; mt < 2; ++mt)
        #pragma unroll
        for (int nt = 0; nt < 8; ++nt)
            #pragma unroll
            for (int e = 0; e < 4; ++e) acc[mt][nt][e] = 0.f;

    // =================== GEMM1: 2 K-chunks of 128 ===================
    for (int kc = 0; kc < 2; ++kc) {
        const float* src = kc ? g_agg : x;

        // --- convert A chunk: [128 rows][128 k] fp32 -> hi/lo bf16 ---
        #pragma unroll
        for (int j = 0; j < 16; ++j) {
            int i = tid + j * 256;                 // 0..4095
            int r = i >> 5, f4 = i & 31;
            int rr = (r < V) ? r : (V - 1);
            float4 v = *(const float4*)(src + (size_t)(node0 + rr) * 128 + f4 * 4);
            uint32_t h0, l0, h1, l1;
            split2(v.x, v.y, h0, l0);
            split2(v.z, v.w, h1, l1);
            uint32_t off = (uint32_t)(r * PITCH + f4 * 4) * 2;
            asm volatile("st.shared.v2.u32 [%0], {%1, %2};"
                         :: "r"(sb + OFF_A_HI + off), "r"(h0), "r"(h1));
            asm volatile("st.shared.v2.u32 [%0], {%1, %2};"
                         :: "r"(sb + OFF_A_LO + off), "r"(l0), "r"(l1));
        }
        // --- copy W1 chunk: [128 n][128 k] hi/lo ---
        #pragma unroll
        for (int j = 0; j < 8; ++j) {
            int i = tid + j * 256;                 // 0..2047
            int r = i >> 4, f8 = i & 15;
            size_t g = (size_t)r * 256 + kc * 128 + f8 * 8;
            uint4 wh = *(const uint4*)(g_W1hi + g);
            uint4 wl = *(const uint4*)(g_W1lo + g);
            uint32_t off = (uint32_t)(r * PITCH + f8 * 8) * 2;
            asm volatile("st.shared.v4.u32 [%0], {%1, %2, %3, %4};"
                         :: "r"(sb + OFF_W_HI + off), "r"(wh.x), "r"(wh.y), "r"(wh.z), "r"(wh.w));
            asm volatile("st.shared.v4.u32 [%0], {%1, %2, %3, %4};"
                         :: "r"(sb + OFF_W_LO + off), "r"(wl.x), "r"(wl.y), "r"(wl.z), "r"(wl.w));
        }
        __syncthreads();

        // --- mma over 8 k16 steps ---
        #pragma unroll
        for (int ks = 0; ks < 8; ++ks) {
            uint32_t ahi[2][4], alo[2][4];
            #pragma unroll
            for (int mt = 0; mt < 2; ++mt) {
                uint32_t aoff = (uint32_t)((mw + mt * 16 + arow) * PITCH + ks * 16 + acol) * 2;
                ldsm_x4(ahi[mt], sb + OFF_A_HI + aoff);
                ldsm_x4(alo[mt], sb + OFF_A_LO + aoff);
            }
            #pragma unroll
            for (int nt = 0; nt < 8; ++nt) {
                uint32_t boff = (uint32_t)((nw + nt * 8 + brow) * PITCH + ks * 16 + bcol) * 2;
                uint32_t bhi[2], blo[2];
                ldsm_x2(bhi, sb + OFF_W_HI + boff);
                ldsm_x2(blo, sb + OFF_W_LO + boff);
                #pragma unroll
                for (int mt = 0; mt < 2; ++mt) {
                    mma_bf16(acc[mt][nt], ahi[mt], bhi);
                    mma_bf16(acc[mt][nt], alo[mt], bhi);
                    mma_bf16(acc[mt][nt], ahi[mt], blo);
                }
            }
        }
        __syncthreads();
    }

    // =================== Epilogue 1: H = relu(acc + b1) -> A buffers ========
    {
        const int r0 = lane >> 2;
        const int c0 = 2 * (lane & 3);
        #pragma unroll
        for (int mt = 0; mt < 2; ++mt) {
            #pragma unroll
            for (int nt = 0; nt < 8; ++nt) {
                int c = nw + nt * 8 + c0;
                float bb0 = sB1[c], bb1 = sB1[c + 1];
                int rA = mw + mt * 16 + r0;
                float h00 = fmaxf(acc[mt][nt][0] + bb0, 0.f);
                float h01 = fmaxf(acc[mt][nt][1] + bb1, 0.f);
                float h10 = fmaxf(acc[mt][nt][2] + bb0, 0.f);
                float h11 = fmaxf(acc[mt][nt][3] + bb1, 0.f);
                uint32_t hp0, lp0, hp1, lp1;
                split2(h00, h01, hp0, lp0);
                split2(h10, h11, hp1, lp1);
                uint32_t off0 = (uint32_t)(rA * PITCH + c) * 2;
                uint32_t off1 = (uint32_t)((rA + 8) * PITCH + c) * 2;
                asm volatile("st.shared.b32 [%0], %1;" :: "r"(sb + OFF_A_HI + off0), "r"(hp0));
                asm volatile("st.shared.b32 [%0], %1;" :: "r"(sb + OFF_A_LO + off0), "r"(lp0));
                asm volatile("st.shared.b32 [%0], %1;" :: "r"(sb + OFF_A_HI + off1), "r"(hp1));
                asm volatile("st.shared.b32 [%0], %1;" :: "r"(sb + OFF_A_LO + off1), "r"(lp1));
                #pragma unroll
                for (int e = 0; e < 4; ++e) acc[mt][nt][e] = 0.f;
            }
        }
    }
    // --- load W2 [128][128] hi/lo ---
    #pragma unroll
    for (int j = 0; j < 8; ++j) {
        int i = tid + j * 256;
        int r = i >> 4, f8 = i & 15;
        size_t g = (size_t)r * 128 + f8 * 8;
        uint4 wh = *(const uint4*)(g_W2hi + g);
        uint4 wl = *(const uint4*)(g_W2lo + g);
        uint32_t off = (uint32_t)(r * PITCH + f8 * 8) * 2;
        asm volatile("st.shared.v4.u32 [%0], {%1, %2, %3, %4};"
                     :: "r"(sb + OFF_W_HI + off), "r"(wh.x), "r"(wh.y), "r"(wh.z), "r"(wh.w));
        asm volatile("st.shared.v4.u32 [%0], {%1, %2, %3, %4};"
                     :: "r"(sb + OFF_W_LO + off), "r"(wl.x), "r"(wl.y), "r"(wl.z), "r"(wl.w));
    }
    __syncthreads();

    // =================== GEMM2: K=128 ===================
    #pragma unroll
    for (int ks = 0; ks < 8; ++ks) {
        uint32_t ahi[2][4], alo[2][4];
        #pragma unroll
        for (int mt = 0; mt < 2; ++mt) {
            uint32_t aoff = (uint32_t)((mw + mt * 16 + arow) * PITCH + ks * 16 + acol) * 2;
            ldsm_x4(ahi[mt], sb + OFF_A_HI + aoff);
            ldsm_x4(alo[mt], sb + OFF_A_LO + aoff);
        }
        #pragma unroll
        for (int nt = 0; nt < 8; ++nt) {
            uint32_t boff = (uint32_t)((nw + nt * 8 + brow) * PITCH + ks * 16 + bcol) * 2;
            uint32_t bhi[2], blo[2];
            ldsm_x2(bhi, sb + OFF_W_HI + boff);
            ldsm_x2(blo, sb + OFF_W_LO + boff);
            #pragma unroll
            for (int mt = 0; mt < 2; ++mt) {
                mma_bf16(acc[mt][nt], ahi[mt], bhi);
                mma_bf16(acc[mt][nt], alo[mt], bhi);
                mma_bf16(acc[mt][nt], ahi[mt], blo);
            }
        }
    }

    // =================== Epilogue 2: out = acc + b2 ===================
    {
        const int r0 = lane >> 2;
        const int c0 = 2 * (lane & 3);
        #pragma unroll
        for (int mt = 0; mt < 2; ++mt) {
            #pragma unroll
            for (int nt = 0; nt < 8; ++nt) {
                int c = nw + nt * 8 + c0;
                float bb0 = sB2[c], bb1 = sB2[c + 1];
                int r = mw + mt * 16 + r0;
                if (r < V) {
                    *(float2*)(out + (size_t)(node0 + r) * 128 + c) =
                        make_float2(acc[mt][nt][0] + bb0, acc[mt][nt][1] + bb1);
                }
                if (r + 8 < V) {
                    *(float2*)(out + (size_t)(node0 + r + 8) * 128 + c) =
                        make_float2(acc[mt][nt][2] + bb0, acc[mt][nt][3] + bb1);
                }
            }
        }
    }
}

// ---------------------------------------------------------------------------
extern "C" void kernel_launch(void* const* d_in, const int* in_sizes, int n_in,
                              void* d_out, int out_size) {
    const float* x          = (const float*)d_in[0];
    const float* edge_attr  = (const float*)d_in[1];
    const int*   edge_index = (const int*)d_in[2];   // int32
    const float* W1         = (const float*)d_in[3];
    const float* b1         = (const float*)d_in[4];
    const float* W2         = (const float*)d_in[5];
    const float* b2         = (const float*)d_in[6];
    float*       out        = (float*)d_out;

    const int* recv = edge_index + N_EDGES;

    cudaFuncSetAttribute(mma_mlp_kernel,
                         cudaFuncAttributeMaxDynamicSharedMemorySize, SMEM_SZ);

    prep_w_kernel<<<128, 256>>>(W1, W2);
    zero_agg_kernel<<<25000, 256>>>();
    scatter_kernel<<<100000, 256>>>(edge_attr, recv);
    mma_mlp_kernel<<<(N_NODES + 127) / 128, 256, SMEM_SZ>>>(x, b1, b2, out);
}